// round 2
// baseline (speedup 1.0000x reference)
#include <cuda_runtime.h>

// Problem constants (fixed shapes: x = (2, 64, 256, 256) fp32, stoken_size = 16)
#define BB   2
#define CC   64
#define HH   256
#define WW   256
#define SS   16
#define NH   16
#define NW   16
#define NSP  256      // nH*nW
#define NPIX 65536    // H*W

// Scratch (device globals; no allocations allowed)
__device__ float g_cent0[BB*NSP*CC];
__device__ float g_csq0 [BB*NSP];
__device__ float g_cent1[BB*NSP*CC];
__device__ float g_csq1 [BB*NSP];
// per-block partials: [b][blk][k(9)][65]  (c=0..63 -> sum w*p[c], c=64 -> sum w)
__device__ float g_part [BB*NSP*9*65];
// final weights: [b][blk][k(9)][pix(256)]  (contiguous per (blk,k) for float4 reads)
__device__ __align__(16) float g_w [BB*NSP*9*256];

// ---------------------------------------------------------------------------
// K1: initial centroids = per-16x16-block channel means (+ |c|^2 per block)
// grid = B*nS (512), block = 256 (one thread per pixel of the block)
// ---------------------------------------------------------------------------
__global__ __launch_bounds__(256) void k_means(const float* __restrict__ x)
{
    int bid = blockIdx.x;
    int b   = bid >> 8;
    int blk = bid & 255;
    int sy  = blk >> 4, sx = blk & 15;
    int tid = threadIdx.x;
    int ry  = tid >> 4, rx = tid & 15;
    int n   = (sy*SS + ry)*WW + sx*SS + rx;
    const float* xp = x + (size_t)b*CC*NPIX + n;

    __shared__ float wsum[CC][9];   // [channel][warp], padded to 9 (conflict-free)
    int wid = tid >> 5, lane = tid & 31;

    #pragma unroll
    for (int c = 0; c < CC; c++) {
        float v = xp[(size_t)c*NPIX];
        #pragma unroll
        for (int o = 16; o > 0; o >>= 1) v += __shfl_xor_sync(0xffffffffu, v, o);
        if (lane == 0) wsum[c][wid] = v;
    }
    __syncthreads();

    float sq = 0.f;
    if (tid < CC) {
        float s = 0.f;
        #pragma unroll
        for (int w = 0; w < 8; w++) s += wsum[tid][w];
        float m = s * (1.f/256.f);
        g_cent0[((size_t)(b*NSP + blk))*CC + tid] = m;
        sq = m*m;
    }
    #pragma unroll
    for (int o = 16; o > 0; o >>= 1) sq += __shfl_xor_sync(0xffffffffu, sq, o);
    __shared__ float sqw[8];
    if (lane == 0) sqw[wid] = sq;
    __syncthreads();
    if (tid == 0) {
        float t = 0.f;
        #pragma unroll
        for (int w = 0; w < 8; w++) t += sqw[w];
        g_csq0[b*NSP + blk] = t;
    }
}

// ---------------------------------------------------------------------------
// K2: iteration 0. Per-block softmax weights + per-block partial sums for the
// centroid update (register-blocked small matmul in smem).
// grid = 512, block = 256, dynamic smem = 77120 B.
// ---------------------------------------------------------------------------
__global__ __launch_bounds__(256, 2) void k_iter0(const float* __restrict__ x)
{
    extern __shared__ float sm[];
    float4* Psh    = (float4*)sm;            // [16][256] pixel features (channel quads)
    float*  Wsh    = sm + 16*256*4;          // [256][9] weights
    float*  cent_s = Wsh + 256*9;            // [9][64]
    float*  csq_s  = cent_s + 9*64;          // [9]

    int bid = blockIdx.x;
    int b   = bid >> 8;
    int blk = bid & 255;
    int sy  = blk >> 4, sx = blk & 15;
    int tid = threadIdx.x;

    for (int i = tid; i < 9*64; i += 256) {
        int k = i >> 6, c = i & 63;
        int cy = sy + (k/3) - 1, cx = sx + (k%3) - 1;
        float v = 0.f;
        if (cy >= 0 && cy < NH && cx >= 0 && cx < NW)
            v = g_cent0[((size_t)(b*NSP + cy*NW + cx))*CC + c];
        cent_s[i] = v;
    }
    if (tid < 9) {
        int cy = sy + (tid/3) - 1, cx = sx + (tid%3) - 1;
        csq_s[tid] = (cy >= 0 && cy < NH && cx >= 0 && cx < NW)
                     ? g_csq0[b*NSP + cy*NW + cx] : 0.f;
    }
    __syncthreads();

    int ry = tid >> 4, rx = tid & 15;
    int n  = (sy*SS + ry)*WW + sx*SS + rx;
    const float* xp = x + (size_t)b*CC*NPIX + n;

    float dot[9];
    #pragma unroll
    for (int k = 0; k < 9; k++) dot[k] = 0.f;

    #pragma unroll 4
    for (int c4 = 0; c4 < 16; c4++) {
        float4 p;
        p.x = xp[(size_t)(c4*4 + 0)*NPIX];
        p.y = xp[(size_t)(c4*4 + 1)*NPIX];
        p.z = xp[(size_t)(c4*4 + 2)*NPIX];
        p.w = xp[(size_t)(c4*4 + 3)*NPIX];
        Psh[c4*256 + tid] = p;
        #pragma unroll
        for (int k = 0; k < 9; k++) {
            float4 cv = *(const float4*)(cent_s + k*64 + c4*4);
            dot[k] = fmaf(p.x, cv.x, dot[k]);
            dot[k] = fmaf(p.y, cv.y, dot[k]);
            dot[k] = fmaf(p.z, cv.z, dot[k]);
            dot[k] = fmaf(p.w, cv.w, dot[k]);
        }
    }

    float l[9];
    float m = -1e30f;
    #pragma unroll
    for (int k = 0; k < 9; k++) {
        int cy = sy + (k/3) - 1, cx = sx + (k%3) - 1;
        bool valid = (cy >= 0 && cy < NH && cx >= 0 && cx < NW);
        l[k] = valid ? (2.f*dot[k] - csq_s[k]) : -1e30f;
        m = fmaxf(m, l[k]);
    }
    float e[9], ssum = 0.f;
    #pragma unroll
    for (int k = 0; k < 9; k++) {
        e[k] = (l[k] > -1e29f) ? __expf(l[k] - m) : 0.f;
        ssum += e[k];
    }
    float inv = 1.f / ssum;
    #pragma unroll
    for (int k = 0; k < 9; k++) Wsh[tid*9 + k] = e[k]*inv;

    __syncthreads();

    // partial[k][c] = sum_pix Wsh[pix][k] * Psh[c][pix]
    if (tid < 144) {
        int k = tid >> 4, c4 = tid & 15;
        float4 acc = make_float4(0.f, 0.f, 0.f, 0.f);
        #pragma unroll 8
        for (int pix = 0; pix < 256; pix++) {
            float  w = Wsh[pix*9 + k];
            float4 p = Psh[c4*256 + pix];
            acc.x = fmaf(w, p.x, acc.x);
            acc.y = fmaf(w, p.y, acc.y);
            acc.z = fmaf(w, p.z, acc.z);
            acc.w = fmaf(w, p.w, acc.w);
        }
        float* dst = g_part + ((size_t)((b*NSP + blk)*9 + k))*65 + c4*4;
        dst[0] = acc.x; dst[1] = acc.y; dst[2] = acc.z; dst[3] = acc.w;
    } else if (tid < 153) {
        int k = tid - 144;
        float s = 0.f;
        #pragma unroll 8
        for (int pix = 0; pix < 256; pix++) s += Wsh[pix*9 + k];
        g_part[((size_t)((b*NSP + blk)*9 + k))*65 + 64] = s;
    }
}

// ---------------------------------------------------------------------------
// K3: gather per-superpixel centroid update (no atomics)
// grid = 512 (b,s), block = 64 (one thread per channel)
// ---------------------------------------------------------------------------
__global__ __launch_bounds__(64) void k_update()
{
    int bid = blockIdx.x;
    int b   = bid >> 8;
    int s   = bid & 255;
    int sy  = s >> 4, sx = s & 15;
    int c   = threadIdx.x;

    float num = 0.f, den = 0.f;
    #pragma unroll
    for (int j = 0; j < 9; j++) {
        int dy = j/3 - 1, dx = j%3 - 1;
        int ny = sy + dy, nx = sx + dx;
        if (ny >= 0 && ny < NH && nx >= 0 && nx < NW) {
            int nb = ny*NW + nx;
            const float* p = g_part + ((size_t)((b*NSP + nb)*9 + (8 - j)))*65;
            num += p[c];
            den += p[64];
        }
    }
    float mval = num / (den + 1e-16f);
    g_cent1[((size_t)(b*NSP + s))*CC + c] = mval;

    float sq = mval*mval;
    #pragma unroll
    for (int o = 16; o > 0; o >>= 1) sq += __shfl_xor_sync(0xffffffffu, sq, o);
    __shared__ float t2[2];
    if ((c & 31) == 0) t2[c >> 5] = sq;
    __syncthreads();
    if (c == 0) g_csq1[b*NSP + s] = t2[0] + t2[1];
}

// ---------------------------------------------------------------------------
// K4: iteration 1 weights against updated centroids -> g_w[b][blk][k][pix]
// (no scatter into the output; contiguous per (blk,k) so the writer reads f4)
// grid = 512, block = 256.
// ---------------------------------------------------------------------------
__global__ __launch_bounds__(256) void k_weights(const float* __restrict__ x)
{
    __shared__ __align__(16) float cent_s[9*64];
    __shared__ float csq_s[9];

    int bid = blockIdx.x;
    int b   = bid >> 8;
    int blk = bid & 255;
    int sy  = blk >> 4, sx = blk & 15;
    int tid = threadIdx.x;

    for (int i = tid; i < 9*64; i += 256) {
        int k = i >> 6, c = i & 63;
        int cy = sy + (k/3) - 1, cx = sx + (k%3) - 1;
        float v = 0.f;
        if (cy >= 0 && cy < NH && cx >= 0 && cx < NW)
            v = g_cent1[((size_t)(b*NSP + cy*NW + cx))*CC + c];
        cent_s[i] = v;
    }
    if (tid < 9) {
        int cy = sy + (tid/3) - 1, cx = sx + (tid%3) - 1;
        csq_s[tid] = (cy >= 0 && cy < NH && cx >= 0 && cx < NW)
                     ? g_csq1[b*NSP + cy*NW + cx] : 0.f;
    }
    __syncthreads();

    int ry = tid >> 4, rx = tid & 15;
    int n  = (sy*SS + ry)*WW + sx*SS + rx;
    const float* xp = x + (size_t)b*CC*NPIX + n;

    float dot[9];
    #pragma unroll
    for (int k = 0; k < 9; k++) dot[k] = 0.f;

    #pragma unroll 4
    for (int c4 = 0; c4 < 16; c4++) {
        float4 p;
        p.x = xp[(size_t)(c4*4 + 0)*NPIX];
        p.y = xp[(size_t)(c4*4 + 1)*NPIX];
        p.z = xp[(size_t)(c4*4 + 2)*NPIX];
        p.w = xp[(size_t)(c4*4 + 3)*NPIX];
        #pragma unroll
        for (int k = 0; k < 9; k++) {
            float4 cv = *(const float4*)(cent_s + k*64 + c4*4);
            dot[k] = fmaf(p.x, cv.x, dot[k]);
            dot[k] = fmaf(p.y, cv.y, dot[k]);
            dot[k] = fmaf(p.z, cv.z, dot[k]);
            dot[k] = fmaf(p.w, cv.w, dot[k]);
        }
    }

    float l[9];
    float m = -1e30f;
    #pragma unroll
    for (int k = 0; k < 9; k++) {
        int cy = sy + (k/3) - 1, cx = sx + (k%3) - 1;
        bool valid = (cy >= 0 && cy < NH && cx >= 0 && cx < NW);
        l[k] = valid ? (2.f*dot[k] - csq_s[k]) : -1e30f;
        m = fmaxf(m, l[k]);
    }
    float e[9], ssum = 0.f;
    #pragma unroll
    for (int k = 0; k < 9; k++) {
        e[k] = (l[k] > -1e29f) ? __expf(l[k] - m) : 0.f;
        ssum += e[k];
    }
    float inv = 1.f / ssum;

    float* wp = g_w + ((size_t)(b*NSP + blk)*9)*256 + tid;
    #pragma unroll
    for (int k = 0; k < 9; k++) wp[k*256] = e[k]*inv;
}

// ---------------------------------------------------------------------------
// K5: streaming output writer. Writes ALL of out (134 MB) exactly once,
// fully coalesced float4 stores. Nonzeros read from g_w (L2-resident).
// grid = BB*NSP*4 = 2048 CTAs, block = 256 threads.
// CTA = (b, s, quadrant of 64 image rows). 16 float4-iterations per thread.
// ---------------------------------------------------------------------------
__global__ __launch_bounds__(256) void k_write(float* __restrict__ out)
{
    int bid = blockIdx.x;
    int b   = bid >> 10;
    int rem = bid & 1023;
    int s   = rem >> 2;
    int q   = rem & 3;
    int sy  = s >> 4, sx = s & 15;
    int y0  = q * 64;

    float4* op = (float4*)(out + ((size_t)(b*NSP + s) << 16)) + (y0 << 6);
    const float4* wbase = (const float4*)g_w;

    int tid = threadIdx.x;
    #pragma unroll
    for (int it = 0; it < 16; it++) {
        int idx = it*256 + tid;          // 0..4095 float4 slots in this quadrant
        int y   = y0 + (idx >> 6);
        int x4  = idx & 63;              // float4 index in row; x = x4*4
        int by  = y >> 4;
        int bx  = x4 >> 2;               // (x4*4)>>4
        int dy  = sy - by;
        int dx  = sx - bx;
        float4 v = make_float4(0.f, 0.f, 0.f, 0.f);
        if (dy >= -1 && dy <= 1 && dx >= -1 && dx <= 1) {
            int k   = (dy + 1)*3 + (dx + 1);
            int blk = by*NW + bx;
            int py  = y & 15;
            int px4 = x4 & 3;            // float4 within block row
            v = wbase[(((size_t)(b*NSP + blk)*9 + k) << 6) + (py << 2) + px4];
        }
        op[idx] = v;
    }
}

// ---------------------------------------------------------------------------
extern "C" void kernel_launch(void* const* d_in, const int* in_sizes, int n_in,
                              void* d_out, int out_size)
{
    const float* x = (const float*)d_in[0];
    float* out = (float*)d_out;

    const int smem_bytes = (16*256*4 + 256*9 + 9*64 + 16) * (int)sizeof(float); // 77120

    k_means<<<BB*NSP, 256>>>(x);
    cudaFuncSetAttribute(k_iter0, cudaFuncAttributeMaxDynamicSharedMemorySize, smem_bytes);
    k_iter0<<<BB*NSP, 256, smem_bytes>>>(x);
    k_update<<<BB*NSP, 64>>>();
    k_weights<<<BB*NSP, 256>>>(x);
    k_write<<<BB*NSP*4, 256>>>(out);
}

// round 3
// speedup vs baseline: 1.6476x; 1.6476x over previous
#include <cuda_runtime.h>

// Problem constants (fixed shapes: x = (2, 64, 256, 256) fp32, stoken_size = 16)
#define BB   2
#define CC   64
#define HH   256
#define WW   256
#define SS   16
#define NH   16
#define NW   16
#define NSP  256      // nH*nW
#define NPIX 65536    // H*W

// Scratch (device globals; no allocations allowed)
__device__ float g_cent0[BB*NSP*CC];
__device__ float g_cent1[BB*NSP*CC];
// per-block partials: [b][blk][k(9)][65]  (c=0..63 -> sum w*p[c], c=64 -> sum w)
__device__ float g_part [BB*NSP*9*65];
// final weights: [b][blk][k(9)][pix(256)]
__device__ __align__(16) float g_w [BB*NSP*9*256];

// ---------------------------------------------------------------------------
// K1: initial centroids = per-16x16-block channel means.
// Fully coalesced: CTA = (b, c, block-row by). 2*64*16 = 2048 CTAs, 256 thr.
// Thread (g, fc): sums rows g*4..g*4+3 at float4-column fc. smem tree reduce.
// ---------------------------------------------------------------------------
__global__ __launch_bounds__(256) void k_means(const float* __restrict__ x)
{
    int bid = blockIdx.x;
    int by  = bid & 15;
    int bc  = bid >> 4;          // b*64 + c
    int b   = bc >> 6, c = bc & 63;

    const float4* xp = (const float4*)(x + (size_t)bc*NPIX + (size_t)by*16*WW);
    int tid = threadIdx.x;
    int fc  = tid & 63;          // float4 column 0..63
    int g   = tid >> 6;          // row group 0..3

    float4 s = make_float4(0.f, 0.f, 0.f, 0.f);
    #pragma unroll
    for (int r = 0; r < 4; r++) {
        float4 v = xp[(g*4 + r)*64 + fc];
        s.x += v.x; s.y += v.y; s.z += v.z; s.w += v.w;
    }

    __shared__ float4 sm4[4][64];
    __shared__ float  smc[64];
    sm4[g][fc] = s;
    __syncthreads();

    if (tid < 64) {
        float4 a = sm4[0][tid], b4 = sm4[1][tid], c4 = sm4[2][tid], d4 = sm4[3][tid];
        float h = (a.x+a.y+a.z+a.w) + (b4.x+b4.y+b4.z+b4.w)
                + (c4.x+c4.y+c4.z+c4.w) + (d4.x+d4.y+d4.z+d4.w);
        smc[tid] = h;
    }
    __syncthreads();

    if (tid < 16) {
        float m = (smc[4*tid] + smc[4*tid+1] + smc[4*tid+2] + smc[4*tid+3]) * (1.f/256.f);
        g_cent0[((size_t)(b*NSP + by*16 + tid))*CC + c] = m;
    }
}

// ---------------------------------------------------------------------------
// K2: iteration 0. Phase A: stage 9 candidate centroids + compute |c|^2.
// Phase B: per-pixel dots + softmax -> Wsh. Phase C: per-block partials
// partial[k][c] = sum_pix w*p via warp-per-4-channel coalesced re-read of the
// tile (L1/L2 hit) + butterfly reduction. smem ~11.6 KB (high occupancy).
// grid = 512, block = 256.
// ---------------------------------------------------------------------------
__global__ __launch_bounds__(256) void k_iter0(const float* __restrict__ x)
{
    __shared__ __align__(16) float cent_s[9*64];
    __shared__ float csq_s[9];
    __shared__ float Wsh[256*9];

    int bid = blockIdx.x;
    int b   = bid >> 8;
    int blk = bid & 255;
    int sy  = blk >> 4, sx = blk & 15;
    int tid = threadIdx.x;

    for (int i = tid; i < 9*64; i += 256) {
        int k = i >> 6, c = i & 63;
        int cy = sy + (k/3) - 1, cx = sx + (k%3) - 1;
        float v = 0.f;
        if (cy >= 0 && cy < NH && cx >= 0 && cx < NW)
            v = g_cent0[((size_t)(b*NSP + cy*NW + cx))*CC + c];
        cent_s[i] = v;
    }
    __syncthreads();
    if (tid < 9) {
        float s = 0.f;
        #pragma unroll 8
        for (int c = 0; c < 64; c++) { float v = cent_s[tid*64 + c]; s = fmaf(v, v, s); }
        csq_s[tid] = s;
    }
    __syncthreads();

    // phase B
    int ry = tid >> 4, rx = tid & 15;
    int n  = (sy*SS + ry)*WW + sx*SS + rx;
    const float* xp = x + (size_t)b*CC*NPIX + n;

    float dot[9];
    #pragma unroll
    for (int k = 0; k < 9; k++) dot[k] = 0.f;

    #pragma unroll 4
    for (int c4 = 0; c4 < 16; c4++) {
        float4 p;
        p.x = xp[(size_t)(c4*4 + 0)*NPIX];
        p.y = xp[(size_t)(c4*4 + 1)*NPIX];
        p.z = xp[(size_t)(c4*4 + 2)*NPIX];
        p.w = xp[(size_t)(c4*4 + 3)*NPIX];
        #pragma unroll
        for (int k = 0; k < 9; k++) {
            float4 cv = *(const float4*)(cent_s + k*64 + c4*4);
            dot[k] = fmaf(p.x, cv.x, dot[k]);
            dot[k] = fmaf(p.y, cv.y, dot[k]);
            dot[k] = fmaf(p.z, cv.z, dot[k]);
            dot[k] = fmaf(p.w, cv.w, dot[k]);
        }
    }

    float l[9];
    float m = -1e30f;
    #pragma unroll
    for (int k = 0; k < 9; k++) {
        int cy = sy + (k/3) - 1, cx = sx + (k%3) - 1;
        bool valid = (cy >= 0 && cy < NH && cx >= 0 && cx < NW);
        l[k] = valid ? (2.f*dot[k] - csq_s[k]) : -1e30f;
        m = fmaxf(m, l[k]);
    }
    float e[9], ssum = 0.f;
    #pragma unroll
    for (int k = 0; k < 9; k++) {
        e[k] = (l[k] > -1e29f) ? __expf(l[k] - m) : 0.f;
        ssum += e[k];
    }
    float inv = 1.f / ssum;
    #pragma unroll
    for (int k = 0; k < 9; k++) Wsh[tid*9 + k] = e[k]*inv;

    __syncthreads();

    // phase C: warp w handles channels [w*8, w*8+8) in 2 groups of 4.
    int wid = tid >> 5, lane = tid & 31;
    const float* xt = x + (size_t)b*CC*NPIX + (size_t)(sy*SS)*WW + sx*SS;
    float* pdst = g_part + ((size_t)(b*NSP + blk)*9)*65;

    #pragma unroll
    for (int grp = 0; grp < 2; grp++) {
        int cbase = wid*8 + grp*4;
        float acc[4][9];
        #pragma unroll
        for (int cc = 0; cc < 4; cc++)
            #pragma unroll
            for (int k = 0; k < 9; k++) acc[cc][k] = 0.f;

        #pragma unroll
        for (int j = 0; j < 8; j++) {
            int pix = j*32 + lane;
            int row = pix >> 4, col = pix & 15;
            float w[9];
            #pragma unroll
            for (int k = 0; k < 9; k++) w[k] = Wsh[pix*9 + k];
            #pragma unroll
            for (int cc = 0; cc < 4; cc++) {
                float p = xt[(size_t)(cbase + cc)*NPIX + row*WW + col];
                #pragma unroll
                for (int k = 0; k < 9; k++) acc[cc][k] = fmaf(w[k], p, acc[cc][k]);
            }
        }
        #pragma unroll
        for (int cc = 0; cc < 4; cc++)
            #pragma unroll
            for (int k = 0; k < 9; k++)
                #pragma unroll
                for (int o = 16; o > 0; o >>= 1)
                    acc[cc][k] += __shfl_xor_sync(0xffffffffu, acc[cc][k], o);
        #pragma unroll
        for (int k = 0; k < 9; k++) {
            if (lane == k) {
                #pragma unroll
                for (int cc = 0; cc < 4; cc++)
                    pdst[(size_t)k*65 + cbase + cc] = acc[cc][k];
            }
        }
    }

    // den[k] = sum_pix w[pix][k]  (9 threads; runs concurrently with phase C tails)
    if (tid < 9) {
        float s = 0.f;
        #pragma unroll 8
        for (int pix = 0; pix < 256; pix++) s += Wsh[pix*9 + tid];
        pdst[(size_t)tid*65 + 64] = s;
    }
}

// ---------------------------------------------------------------------------
// K3: gather per-superpixel centroid update (no atomics)
// grid = 512 (b,s), block = 64 (one thread per channel)
// ---------------------------------------------------------------------------
__global__ __launch_bounds__(64) void k_update()
{
    int bid = blockIdx.x;
    int b   = bid >> 8;
    int s   = bid & 255;
    int sy  = s >> 4, sx = s & 15;
    int c   = threadIdx.x;

    float num = 0.f, den = 0.f;
    #pragma unroll
    for (int j = 0; j < 9; j++) {
        int dy = j/3 - 1, dx = j%3 - 1;
        int ny = sy + dy, nx = sx + dx;
        if (ny >= 0 && ny < NH && nx >= 0 && nx < NW) {
            int nb = ny*NW + nx;
            const float* p = g_part + ((size_t)((b*NSP + nb)*9 + (8 - j)))*65;
            num += p[c];
            den += p[64];
        }
    }
    g_cent1[((size_t)(b*NSP + s))*CC + c] = num / (den + 1e-16f);
}

// ---------------------------------------------------------------------------
// K4: iteration 1 weights against updated centroids -> g_w[b][blk][k][pix]
// grid = 512, block = 256.
// ---------------------------------------------------------------------------
__global__ __launch_bounds__(256) void k_weights(const float* __restrict__ x)
{
    __shared__ __align__(16) float cent_s[9*64];
    __shared__ float csq_s[9];

    int bid = blockIdx.x;
    int b   = bid >> 8;
    int blk = bid & 255;
    int sy  = blk >> 4, sx = blk & 15;
    int tid = threadIdx.x;

    for (int i = tid; i < 9*64; i += 256) {
        int k = i >> 6, c = i & 63;
        int cy = sy + (k/3) - 1, cx = sx + (k%3) - 1;
        float v = 0.f;
        if (cy >= 0 && cy < NH && cx >= 0 && cx < NW)
            v = g_cent1[((size_t)(b*NSP + cy*NW + cx))*CC + c];
        cent_s[i] = v;
    }
    __syncthreads();
    if (tid < 9) {
        float s = 0.f;
        #pragma unroll 8
        for (int c = 0; c < 64; c++) { float v = cent_s[tid*64 + c]; s = fmaf(v, v, s); }
        csq_s[tid] = s;
    }
    __syncthreads();

    int ry = tid >> 4, rx = tid & 15;
    int n  = (sy*SS + ry)*WW + sx*SS + rx;
    const float* xp = x + (size_t)b*CC*NPIX + n;

    float dot[9];
    #pragma unroll
    for (int k = 0; k < 9; k++) dot[k] = 0.f;

    #pragma unroll 4
    for (int c4 = 0; c4 < 16; c4++) {
        float4 p;
        p.x = xp[(size_t)(c4*4 + 0)*NPIX];
        p.y = xp[(size_t)(c4*4 + 1)*NPIX];
        p.z = xp[(size_t)(c4*4 + 2)*NPIX];
        p.w = xp[(size_t)(c4*4 + 3)*NPIX];
        #pragma unroll
        for (int k = 0; k < 9; k++) {
            float4 cv = *(const float4*)(cent_s + k*64 + c4*4);
            dot[k] = fmaf(p.x, cv.x, dot[k]);
            dot[k] = fmaf(p.y, cv.y, dot[k]);
            dot[k] = fmaf(p.z, cv.z, dot[k]);
            dot[k] = fmaf(p.w, cv.w, dot[k]);
        }
    }

    float l[9];
    float m = -1e30f;
    #pragma unroll
    for (int k = 0; k < 9; k++) {
        int cy = sy + (k/3) - 1, cx = sx + (k%3) - 1;
        bool valid = (cy >= 0 && cy < NH && cx >= 0 && cx < NW);
        l[k] = valid ? (2.f*dot[k] - csq_s[k]) : -1e30f;
        m = fmaxf(m, l[k]);
    }
    float e[9], ssum = 0.f;
    #pragma unroll
    for (int k = 0; k < 9; k++) {
        e[k] = (l[k] > -1e29f) ? __expf(l[k] - m) : 0.f;
        ssum += e[k];
    }
    float inv = 1.f / ssum;

    float* wp = g_w + ((size_t)(b*NSP + blk)*9)*256 + tid;
    #pragma unroll
    for (int k = 0; k < 9; k++) wp[k*256] = e[k]*inv;
}

// ---------------------------------------------------------------------------
// K5: streaming output writer (writes all 134 MB exactly once, STG.128).
// grid = BB*NSP*4 = 2048 CTAs, block = 256.
// ---------------------------------------------------------------------------
__global__ __launch_bounds__(256) void k_write(float* __restrict__ out)
{
    int bid = blockIdx.x;
    int b   = bid >> 10;
    int rem = bid & 1023;
    int s   = rem >> 2;
    int q   = rem & 3;
    int sy  = s >> 4, sx = s & 15;
    int y0  = q * 64;

    float4* op = (float4*)(out + ((size_t)(b*NSP + s) << 16)) + (y0 << 6);
    const float4* wbase = (const float4*)g_w;

    int tid = threadIdx.x;
    #pragma unroll
    for (int it = 0; it < 16; it++) {
        int idx = it*256 + tid;
        int y   = y0 + (idx >> 6);
        int x4  = idx & 63;
        int by  = y >> 4;
        int bx  = x4 >> 2;
        int dy  = sy - by;
        int dx  = sx - bx;
        float4 v = make_float4(0.f, 0.f, 0.f, 0.f);
        if (dy >= -1 && dy <= 1 && dx >= -1 && dx <= 1) {
            int k   = (dy + 1)*3 + (dx + 1);
            int blk = by*NW + bx;
            int py  = y & 15;
            int px4 = x4 & 3;
            v = wbase[(((size_t)(b*NSP + blk)*9 + k) << 6) + (py << 2) + px4];
        }
        op[idx] = v;
    }
}

// ---------------------------------------------------------------------------
extern "C" void kernel_launch(void* const* d_in, const int* in_sizes, int n_in,
                              void* d_out, int out_size)
{
    const float* x = (const float*)d_in[0];
    float* out = (float*)d_out;

    k_means<<<BB*CC*16, 256>>>(x);
    k_iter0<<<BB*NSP, 256>>>(x);
    k_update<<<BB*NSP, 64>>>();
    k_weights<<<BB*NSP, 256>>>(x);
    k_write<<<BB*NSP*4, 256>>>(out);
}